// round 14
// baseline (speedup 1.0000x reference)
#include <cuda_runtime.h>
#include <cuda_fp16.h>
#include <cstdint>

#define DIM_NODE 64
#define DIM_EDGE 32
#define D_IN1    160
#define OUT_DIM  64
#define MAX_NODES 50000
#define E_TILE   128
#define NEG_SLOPE 0.01f

// Per-node precomputed partials (fp16): P[n][0:128] = x[n]@W1a^T, P[n][128:256] = x[n]@W1b^T
__device__ __half g_P[(size_t)MAX_NODES * 256];
__device__ unsigned g_barrier;   // epoch-accumulating grid barrier counter

__device__ __forceinline__ void mma_f16(float* d, const uint32_t* a, const uint32_t* b) {
    asm volatile(
        "mma.sync.aligned.m16n8k16.row.col.f32.f16.f16.f32 "
        "{%0,%1,%2,%3}, {%4,%5,%6,%7}, {%8,%9}, {%0,%1,%2,%3};"
        : "+f"(d[0]), "+f"(d[1]), "+f"(d[2]), "+f"(d[3])
        : "r"(a[0]), "r"(a[1]), "r"(a[2]), "r"(a[3]), "r"(b[0]), "r"(b[1]));
}
__device__ __forceinline__ void ldsm_x4(uint32_t* r, uint32_t addr) {
    asm volatile("ldmatrix.sync.aligned.m8n8.x4.shared.b16 {%0,%1,%2,%3}, [%4];"
        : "=r"(r[0]), "=r"(r[1]), "=r"(r[2]), "=r"(r[3]) : "r"(addr));
}
__device__ __forceinline__ uint32_t smem_u32(const void* p) {
    uint32_t a;
    asm("{ .reg .u64 t; cvta.to.shared.u64 t, %1; cvt.u32.u64 %0, t; }" : "=r"(a) : "l"(p));
    return a;
}
__device__ __forceinline__ uint32_t pack_h2(float a, float b) {
    __half2 h = __floats2half2_rn(a, b);
    return *(uint32_t*)&h;
}
__device__ __forceinline__ float2 h2f2(uint32_t u) {
    __half2 h = *(__half2*)&u;
    return __half22float2(h);
}

// ---------------------------------------------------------------------------
// SMEM layout (BYTE offsets).
// Phase 1 overlay: XT @0 [128][144B], V @18432 [256][144B], PH @55296 [128][272B]
// Phase 2: H @0 (34816), PS @34816 (34816), EA @69632 (10240, OWN region),
//          W1C @79872 (10240), W2 @90112 (17408), b1 @107520, b2 @108032
// ---------------------------------------------------------------------------
#define PRE_XT_B  0u
#define PRE_V_B   18432u
#define PRE_PH_B  55296u

#define H_B     0u
#define PS_B    34816u
#define EA_B    69632u
#define W1C_B   79872u
#define W2_B    90112u
#define B1_B    107520u
#define B2_B    108032u
#define SMEM_BYTES 108288u

// ---------------------------------------------------------------------------
// Fused persistent kernel: phase 1 node precompute -> grid barrier -> phase 2
// edge MLP tiles (2 barriers/tile, simple direct-STG epilogue).
// ---------------------------------------------------------------------------
__global__ __launch_bounds__(256, 2) void k_fused(
    const float* __restrict__ x,
    const int*   __restrict__ eidx,
    const float* __restrict__ ea,
    const float* __restrict__ W1,
    const float* __restrict__ b1,
    const float* __restrict__ W2g,
    const float* __restrict__ b2,
    float*       __restrict__ out,
    int n_nodes, int E, int n_tiles, int n_node_tiles)
{
    extern __shared__ __align__(16) char smc[];
    const uint32_t sb = smem_u32(smc);
    const int t   = threadIdx.x;
    const int wid = t >> 5;
    const int lid = t & 31;
    const int qr  = lid >> 2;
    const int ql  = lid & 3;
    const int wm  = wid & 3;       // M quadrant (rows wm*32..+32)
    const int wn  = wid >> 2;      // 0/1: h K-half AND output N-half
    const int lm  = lid & 7;
    const int lq3 = lid >> 3;
    const int lq4 = lid >> 4;

    // ======================= PHASE 1: node precompute =======================
    {
        {   // stage V (combined 256x64 weight): fp16 [256][144B]
            int c = t;
            const float* src = (c < 128) ? (W1 + c * D_IN1) : (W1 + (c - 128) * D_IN1 + 64);
            #pragma unroll
            for (int s = 0; s < 4; ++s) {
                float4 v0 = *(const float4*)(src + s * 16 + 0);
                float4 v1 = *(const float4*)(src + s * 16 + 4);
                float4 v2 = *(const float4*)(src + s * 16 + 8);
                float4 v3 = *(const float4*)(src + s * 16 + 12);
                uint4 pa = make_uint4(pack_h2(v0.x, v0.y), pack_h2(v0.z, v0.w),
                                      pack_h2(v1.x, v1.y), pack_h2(v1.z, v1.w));
                uint4 pb = make_uint4(pack_h2(v2.x, v2.y), pack_h2(v2.z, v2.w),
                                      pack_h2(v3.x, v3.y), pack_h2(v3.z, v3.w));
                *(uint4*)(smc + PRE_V_B + c * 144 + s * 32)      = pa;
                *(uint4*)(smc + PRE_V_B + c * 144 + s * 32 + 16) = pb;
            }
        }
        uint32_t ab[2];
        #pragma unroll
        for (int i = 0; i < 2; ++i)
            ab[i] = sb + PRE_XT_B + (uint32_t)((wm * 32 + i * 16 + ((lq3 & 1) << 3) + lm) * 144)
                  + (uint32_t)((lq3 >> 1) * 16);

        for (int nt = blockIdx.x; nt < n_node_tiles; nt += gridDim.x) {
            const int node0 = nt * 128;
            {   // stage x tile fp16 [128][144B]
                int m = t >> 1, hs = t & 1;
                int gn = node0 + m;
                #pragma unroll
                for (int s = 0; s < 2; ++s) {
                    float4 v0, v1, v2, v3;
                    if (gn < n_nodes) {
                        const float4* src = (const float4*)(x + (size_t)gn * DIM_NODE + hs * 32 + s * 16);
                        v0 = src[0]; v1 = src[1]; v2 = src[2]; v3 = src[3];
                    } else {
                        v0 = v1 = v2 = v3 = make_float4(0.f, 0.f, 0.f, 0.f);
                    }
                    uint4 pa = make_uint4(pack_h2(v0.x, v0.y), pack_h2(v0.z, v0.w),
                                          pack_h2(v1.x, v1.y), pack_h2(v1.z, v1.w));
                    uint4 pb = make_uint4(pack_h2(v2.x, v2.y), pack_h2(v2.z, v2.w),
                                          pack_h2(v3.x, v3.y), pack_h2(v3.z, v3.w));
                    *(uint4*)(smc + PRE_XT_B + m * 144 + hs * 64 + s * 32)      = pa;
                    *(uint4*)(smc + PRE_XT_B + m * 144 + hs * 64 + s * 32 + 16) = pb;
                }
            }
            __syncthreads();

            #pragma unroll
            for (int nh = 0; nh < 2; ++nh) {
                if (nh) __syncthreads();
                float acc[2][8][4];
                #pragma unroll
                for (int i = 0; i < 2; ++i)
                    #pragma unroll
                    for (int j = 0; j < 8; ++j)
                        #pragma unroll
                        for (int c = 0; c < 4; ++c) acc[i][j][c] = 0.f;
                #pragma unroll
                for (int ks = 0; ks < 4; ++ks) {
                    uint32_t A[2][4], B[4][4];
                    ldsm_x4(A[0], ab[0] + ks * 32);
                    ldsm_x4(A[1], ab[1] + ks * 32);
                    #pragma unroll
                    for (int jj = 0; jj < 4; ++jj) {
                        int n = nh * 128 + wn * 64 + jj * 16 + lq4 * 8 + lm;
                        ldsm_x4(B[jj], sb + PRE_V_B + (uint32_t)(n * 144)
                                       + (uint32_t)((lq3 & 1) * 16) + ks * 32);
                    }
                    #pragma unroll
                    for (int i = 0; i < 2; ++i)
                        #pragma unroll
                        for (int j = 0; j < 8; ++j)
                            mma_f16(acc[i][j], A[i], &B[j >> 1][(j & 1) * 2]);
                }
                #pragma unroll
                for (int i = 0; i < 2; ++i) {
                    int r = wm * 32 + i * 16 + qr;
                    #pragma unroll
                    for (int j = 0; j < 8; ++j) {
                        int c = wn * 64 + j * 8 + 2 * ql;
                        *(uint32_t*)(smc + PRE_PH_B + r * 272 + 2 * c) =
                            pack_h2(acc[i][j][0], acc[i][j][1]);
                        *(uint32_t*)(smc + PRE_PH_B + (r + 8) * 272 + 2 * c) =
                            pack_h2(acc[i][j][2], acc[i][j][3]);
                    }
                }
                __syncthreads();
                {
                    int m = t >> 1, hs = t & 1;
                    int gn = node0 + m;
                    if (gn < n_nodes) {
                        const uint4* srcp = (const uint4*)(smc + PRE_PH_B + m * 272 + hs * 128);
                        uint4* dstp = (uint4*)((__half*)g_P + (size_t)gn * 256 + nh * 128 + hs * 64);
                        #pragma unroll
                        for (int s = 0; s < 8; ++s) dstp[s] = srcp[s];
                    }
                }
            }
            __syncthreads();
        }
    }

    // ======================= GRID BARRIER (epoch-based) ======================
    __threadfence();
    __syncthreads();
    if (t == 0) {
        unsigned v = *((volatile unsigned*)&g_barrier);
        unsigned target = (v / gridDim.x + 1u) * gridDim.x;
        atomicAdd(&g_barrier, 1u);
        while (*((volatile unsigned*)&g_barrier) < target) { }
    }
    __syncthreads();

    // ======================= PHASE 2 prologue: weights =======================
    {
        int n = t >> 1, hs = t & 1;
        const float4* src = (const float4*)(W1 + n * D_IN1 + 128 + hs * 16);
        float4 v0 = src[0], v1 = src[1], v2 = src[2], v3 = src[3];
        uint4 p0 = make_uint4(pack_h2(v0.x, v0.y), pack_h2(v0.z, v0.w),
                              pack_h2(v1.x, v1.y), pack_h2(v1.z, v1.w));
        uint4 p1 = make_uint4(pack_h2(v2.x, v2.y), pack_h2(v2.z, v2.w),
                              pack_h2(v3.x, v3.y), pack_h2(v3.z, v3.w));
        *(uint4*)(smc + W1C_B + n * 80 + hs * 32)      = p0;
        *(uint4*)(smc + W1C_B + n * 80 + hs * 32 + 16) = p1;
    }
    {
        int n = t >> 2, q = t & 3;
        const float4* src = (const float4*)(W2g + n * 128 + q * 32);
        #pragma unroll
        for (int s = 0; s < 2; ++s) {
            float4 v0 = src[4 * s + 0], v1 = src[4 * s + 1],
                   v2 = src[4 * s + 2], v3 = src[4 * s + 3];
            uint4 pa = make_uint4(pack_h2(v0.x, v0.y), pack_h2(v0.z, v0.w),
                                  pack_h2(v1.x, v1.y), pack_h2(v1.z, v1.w));
            uint4 pb = make_uint4(pack_h2(v2.x, v2.y), pack_h2(v2.z, v2.w),
                                  pack_h2(v3.x, v3.y), pack_h2(v3.z, v3.w));
            *(uint4*)(smc + W2_B + n * 272 + q * 64 + s * 32)      = pa;
            *(uint4*)(smc + W2_B + n * 272 + q * 64 + s * 32 + 16) = pb;
        }
    }
    if (t < 128)      ((float*)(smc + B1_B))[t] = b1[t];
    else if (t < 192) ((float*)(smc + B2_B))[t - 128] = b2[t - 128];
    __syncthreads();

    float2 bb2[4];
    #pragma unroll
    for (int j = 0; j < 4; ++j)
        bb2[j] = *(const float2*)((float*)(smc + B2_B) + wn * 32 + j * 8 + 2 * ql);
    const float4 bb1 = *(const float4*)((float*)(smc + B1_B) + 4 * lid);

    // ---- ldmatrix per-lane base addresses ----
    uint32_t a1b[2], b1b[4], a2o[2], b2b[2];
    #pragma unroll
    for (int i = 0; i < 2; ++i)
        a1b[i] = sb + EA_B + (uint32_t)((wm * 32 + i * 16 + ((lq3 & 1) << 3) + lm) * 80)
               + (uint32_t)((lq3 >> 1) * 16);
    #pragma unroll
    for (int jj = 0; jj < 4; ++jj)
        b1b[jj] = sb + W1C_B + (uint32_t)((wn * 64 + jj * 16 + lq4 * 8 + lm) * 80)
                + (uint32_t)((lq3 & 1) * 16);
    #pragma unroll
    for (int i = 0; i < 2; ++i)
        a2o[i] = sb + H_B + (uint32_t)((wm * 32 + i * 16 + ((lq3 & 1) << 3) + lm) * 272)
               + (uint32_t)((lq3 >> 1) * 16) + (uint32_t)((wn ^ 1) * 128);
    #pragma unroll
    for (int jj = 0; jj < 2; ++jj)
        b2b[jj] = sb + W2_B + (uint32_t)((wn * 32 + jj * 16 + lq4 * 8 + lm) * 272)
                + (uint32_t)((lq3 & 1) * 16);

    const int m0 = wid * 16;

    // ======================= PHASE 2: edge tile loop =========================
    for (int tile = blockIdx.x; tile < n_tiles; tile += gridDim.x) {
        const int ebase = tile * E_TILE;

        // ---- per-warp edge indices (lanes 0-15 src, 16-31 dst) ----
        int my_idx = 0;
        {
            int eM = ebase + m0 + (lid & 15);
            if (eM < E) my_idx = (lid < 16) ? eidx[eM] : eidx[E + eM];
        }

        // ---- issue all Psum gather LDGs up front ----
        uint2 us0[8], ud0[8], us1[8], ud1[8];
        #pragma unroll
        for (int r = 0; r < 8; ++r) {
            int si = __shfl_sync(0xffffffffu, my_idx, r);
            int di = __shfl_sync(0xffffffffu, my_idx, 16 + r);
            us0[r] = *(const uint2*)((const __half*)g_P + (size_t)si * 256 + 4 * lid);
            ud0[r] = *(const uint2*)((const __half*)g_P + (size_t)di * 256 + 128 + 4 * lid);
        }
        #pragma unroll
        for (int r = 0; r < 8; ++r) {
            int si = __shfl_sync(0xffffffffu, my_idx, 8 + r);
            int di = __shfl_sync(0xffffffffu, my_idx, 24 + r);
            us1[r] = *(const uint2*)((const __half*)g_P + (size_t)si * 256 + 4 * lid);
            ud1[r] = *(const uint2*)((const __half*)g_P + (size_t)di * 256 + 128 + 4 * lid);
        }

        // ---- stage ea -> fp16 [128][40h] (own EA region) ----
        {
            int m = t >> 1, hs = t & 1;
            int ge = ebase + m;
            float4 v0, v1, v2, v3;
            if (ge < E) {
                const float4* src = (const float4*)(ea + (size_t)ge * DIM_EDGE + hs * 16);
                v0 = src[0]; v1 = src[1]; v2 = src[2]; v3 = src[3];
            } else {
                v0 = v1 = v2 = v3 = make_float4(0.f, 0.f, 0.f, 0.f);
            }
            uint4 p0 = make_uint4(pack_h2(v0.x, v0.y), pack_h2(v0.z, v0.w),
                                  pack_h2(v1.x, v1.y), pack_h2(v1.z, v1.w));
            uint4 p1 = make_uint4(pack_h2(v2.x, v2.y), pack_h2(v2.z, v2.w),
                                  pack_h2(v3.x, v3.y), pack_h2(v3.z, v3.w));
            *(uint4*)(smc + EA_B + m * 80 + hs * 32)      = p0;
            *(uint4*)(smc + EA_B + m * 80 + hs * 32 + 16) = p1;
        }

        // ---- Psum = fp16(P_src + P_dst + b1) -> PS ----
        #pragma unroll
        for (int r = 0; r < 8; ++r) {
            float2 s01 = h2f2(us0[r].x), s23 = h2f2(us0[r].y);
            float2 d01 = h2f2(ud0[r].x), d23 = h2f2(ud0[r].y);
            *(uint2*)(smc + PS_B + (m0 + r) * 272 + 8 * lid) =
                make_uint2(pack_h2(s01.x + d01.x + bb1.x, s01.y + d01.y + bb1.y),
                           pack_h2(s23.x + d23.x + bb1.z, s23.y + d23.y + bb1.w));
        }
        #pragma unroll
        for (int r = 0; r < 8; ++r) {
            float2 s01 = h2f2(us1[r].x), s23 = h2f2(us1[r].y);
            float2 d01 = h2f2(ud1[r].x), d23 = h2f2(ud1[r].y);
            *(uint2*)(smc + PS_B + (m0 + 8 + r) * 272 + 8 * lid) =
                make_uint2(pack_h2(s01.x + d01.x + bb1.x, s01.y + d01.y + bb1.y),
                           pack_h2(s23.x + d23.x + bb1.z, s23.y + d23.y + bb1.w));
        }
        __syncthreads();                       // (A) EA + PS staged

        // ---- GEMM1: C1[128x128] = ea @ W1c^T (per warp M=32, N=64) ----
        float acc1[2][8][4];
        #pragma unroll
        for (int i = 0; i < 2; ++i)
            #pragma unroll
            for (int j = 0; j < 8; ++j)
                #pragma unroll
                for (int c = 0; c < 4; ++c) acc1[i][j][c] = 0.f;

        #pragma unroll
        for (int ks = 0; ks < 2; ++ks) {
            uint32_t A[2][4], B[4][4];
            ldsm_x4(A[0], a1b[0] + ks * 32);
            ldsm_x4(A[1], a1b[1] + ks * 32);
            #pragma unroll
            for (int jj = 0; jj < 4; ++jj)
                ldsm_x4(B[jj], b1b[jj] + ks * 32);
            #pragma unroll
            for (int i = 0; i < 2; ++i)
                #pragma unroll
                for (int j = 0; j < 8; ++j)
                    mma_f16(acc1[i][j], A[i], &B[j >> 1][(j & 1) * 2]);
        }

        // ---- convert (no barrier: own acc1 + PS staged at (A)) ----
        uint32_t hA[2][4][4];
        #pragma unroll
        for (int i = 0; i < 2; ++i) {
            const int r0 = wm * 32 + i * 16 + qr;
            const int r1 = r0 + 8;
            #pragma unroll
            for (int ks = 0; ks < 4; ++ks) {
                #pragma unroll
                for (int jj = 0; jj < 2; ++jj) {
                    const int j = 2 * ks + jj;
                    const uint32_t off = (uint32_t)(wn * 128 + j * 16 + ql * 4);
                    float2 p0 = h2f2(*(const uint32_t*)(smc + PS_B + r0 * 272 + off));
                    float2 p1 = h2f2(*(const uint32_t*)(smc + PS_B + r1 * 272 + off));
                    float h0 = acc1[i][j][0] + p0.x;
                    float h1 = acc1[i][j][1] + p0.y;
                    float h2 = acc1[i][j][2] + p1.x;
                    float h3 = acc1[i][j][3] + p1.y;
                    h0 = (h0 >= 0.f) ? h0 : NEG_SLOPE * h0;
                    h1 = (h1 >= 0.f) ? h1 : NEG_SLOPE * h1;
                    h2 = (h2 >= 0.f) ? h2 : NEG_SLOPE * h2;
                    h3 = (h3 >= 0.f) ? h3 : NEG_SLOPE * h3;
                    uint32_t u0 = pack_h2(h0, h1);
                    uint32_t u1 = pack_h2(h2, h3);
                    hA[i][ks][jj * 2 + 0] = u0;
                    hA[i][ks][jj * 2 + 1] = u1;
                    *(uint32_t*)(smc + H_B + r0 * 272 + off) = u0;
                    *(uint32_t*)(smc + H_B + r1 * 272 + off) = u1;
                }
            }
        }
        __syncthreads();                       // (C) h visible for partner

        // ---- GEMM2: own K-half from regs, other via ldsm; M=32, N=32 ----
        float acc2[2][4][4];
        #pragma unroll
        for (int i = 0; i < 2; ++i)
            #pragma unroll
            for (int j = 0; j < 4; ++j)
                #pragma unroll
                for (int c = 0; c < 4; ++c) acc2[i][j][c] = 0.f;

        #pragma unroll
        for (int ksl = 0; ksl < 4; ++ksl) {
            uint32_t B[2][4];
            ldsm_x4(B[0], b2b[0] + (uint32_t)(wn * 128) + ksl * 32);
            ldsm_x4(B[1], b2b[1] + (uint32_t)(wn * 128) + ksl * 32);
            #pragma unroll
            for (int i = 0; i < 2; ++i)
                #pragma unroll
                for (int j = 0; j < 4; ++j)
                    mma_f16(acc2[i][j], hA[i][ksl], &B[j >> 1][(j & 1) * 2]);
        }
        #pragma unroll
        for (int ksl = 0; ksl < 4; ++ksl) {
            uint32_t A[2][4], B[2][4];
            ldsm_x4(A[0], a2o[0] + ksl * 32);
            ldsm_x4(A[1], a2o[1] + ksl * 32);
            ldsm_x4(B[0], b2b[0] + (uint32_t)((wn ^ 1) * 128) + ksl * 32);
            ldsm_x4(B[1], b2b[1] + (uint32_t)((wn ^ 1) * 128) + ksl * 32);
            #pragma unroll
            for (int i = 0; i < 2; ++i)
                #pragma unroll
                for (int j = 0; j < 4; ++j)
                    mma_f16(acc2[i][j], A[i], &B[j >> 1][(j & 1) * 2]);
        }

        // ---- Epilogue: direct STG from C2 fragments (+b2) ----
        #pragma unroll
        for (int i = 0; i < 2; ++i) {
            int r = wm * 32 + i * 16 + qr;
            int ge0 = ebase + r;
            int ge1 = ge0 + 8;
            #pragma unroll
            for (int j = 0; j < 4; ++j) {
                int c = wn * 32 + j * 8 + 2 * ql;
                if (ge0 < E)
                    *(float2*)(out + (size_t)ge0 * OUT_DIM + c) =
                        make_float2(acc2[i][j][0] + bb2[j].x, acc2[i][j][1] + bb2[j].y);
                if (ge1 < E)
                    *(float2*)(out + (size_t)ge1 * OUT_DIM + c) =
                        make_float2(acc2[i][j][2] + bb2[j].x, acc2[i][j][3] + bb2[j].y);
            }
        }
        // no end barrier: next staging writes only EA/PS; all EA/PS readers
        // finished before barrier (C) of this tile.
    }
}

// ---------------------------------------------------------------------------
extern "C" void kernel_launch(void* const* d_in, const int* in_sizes, int n_in,
                              void* d_out, int out_size)
{
    const float* x    = (const float*)d_in[0];
    const int*   eidx = (const int*)  d_in[1];
    const float* ea   = (const float*)d_in[2];
    const float* W1   = (const float*)d_in[3];
    const float* b1   = (const float*)d_in[4];
    const float* W2   = (const float*)d_in[5];
    const float* b2   = (const float*)d_in[6];
    float* out = (float*)d_out;

    int n_nodes = in_sizes[0] / DIM_NODE;
    if (n_nodes > MAX_NODES) n_nodes = MAX_NODES;
    int E = in_sizes[2] / DIM_EDGE;
    int n_tiles = (E + E_TILE - 1) / E_TILE;
    int n_node_tiles = (n_nodes + 127) / 128;

    static int n_sms = 0;
    if (n_sms == 0) {
        int dev = 0;
        cudaGetDevice(&dev);
        cudaDeviceGetAttribute(&n_sms, cudaDevAttrMultiProcessorCount, dev);
        if (n_sms <= 0) n_sms = 148;
    }
    int n_blocks = n_sms * 2;   // all resident (launch_bounds(256,2)) -> grid barrier safe

    cudaFuncSetAttribute(k_fused, cudaFuncAttributeMaxDynamicSharedMemorySize, (int)SMEM_BYTES);
    k_fused<<<n_blocks, 256, SMEM_BYTES>>>(x, eidx, ea, W1, b1, W2, b2, out,
                                           n_nodes, E, n_tiles, n_node_tiles);
}

// round 15
// speedup vs baseline: 1.1550x; 1.1550x over previous
#include <cuda_runtime.h>
#include <cuda_fp16.h>
#include <cstdint>

#define DIM_NODE 64
#define DIM_EDGE 32
#define D_IN1    160
#define OUT_DIM  64
#define MAX_NODES 50000
#define E_TILE   128
#define NEG_SLOPE 0.01f

// Per-node precomputed partials (fp16): P[n][0:128] = x[n]@W1a^T, P[n][128:256] = x[n]@W1b^T
__device__ __half g_P[(size_t)MAX_NODES * 256];
__device__ unsigned g_barrier;   // epoch-accumulating grid barrier counter

__device__ __forceinline__ void mma_f16(float* d, const uint32_t* a, const uint32_t* b) {
    asm volatile(
        "mma.sync.aligned.m16n8k16.row.col.f32.f16.f16.f32 "
        "{%0,%1,%2,%3}, {%4,%5,%6,%7}, {%8,%9}, {%0,%1,%2,%3};"
        : "+f"(d[0]), "+f"(d[1]), "+f"(d[2]), "+f"(d[3])
        : "r"(a[0]), "r"(a[1]), "r"(a[2]), "r"(a[3]), "r"(b[0]), "r"(b[1]));
}
__device__ __forceinline__ void ldsm_x4(uint32_t* r, uint32_t addr) {
    asm volatile("ldmatrix.sync.aligned.m8n8.x4.shared.b16 {%0,%1,%2,%3}, [%4];"
        : "=r"(r[0]), "=r"(r[1]), "=r"(r[2]), "=r"(r[3]) : "r"(addr));
}
__device__ __forceinline__ uint32_t smem_u32(const void* p) {
    uint32_t a;
    asm("{ .reg .u64 t; cvta.to.shared.u64 t, %1; cvt.u32.u64 %0, t; }" : "=r"(a) : "l"(p));
    return a;
}
__device__ __forceinline__ uint32_t pack_h2(float a, float b) {
    __half2 h = __floats2half2_rn(a, b);
    return *(uint32_t*)&h;
}
__device__ __forceinline__ float2 h2f2(uint32_t u) {
    __half2 h = *(__half2*)&u;
    return __half22float2(h);
}

// ---------------------------------------------------------------------------
// SMEM layout (BYTE offsets) — identical to round 12.
// Phase 1 overlay: XT @0 [128][144B], V @18432 [256][144B], PH @55296 [128][272B]
// Phase 2: H/EA @0, PS @34816, W1C @69632, W2 @79872, b1 @97280, b2 @97792
// ---------------------------------------------------------------------------
#define PRE_XT_B  0u
#define PRE_V_B   18432u
#define PRE_PH_B  55296u

#define H_B     0u
#define EA_B    0u
#define PS_B    34816u
#define W1C_B   69632u
#define W2_B    79872u
#define B1_B    97280u
#define B2_B    97792u
#define SMEM_BYTES 98304u

// ---------------------------------------------------------------------------
// Fused persistent kernel (round-12 structure): phase 1 node precompute ->
// grid barrier -> phase 2 edge tiles (4 barriers/tile).  Streaming cache
// hints on ea/x loads and out stores protect g_P's L2 residency.
// ---------------------------------------------------------------------------
__global__ __launch_bounds__(256, 2) void k_fused(
    const float* __restrict__ x,
    const int*   __restrict__ eidx,
    const float* __restrict__ ea,
    const float* __restrict__ W1,
    const float* __restrict__ b1,
    const float* __restrict__ W2g,
    const float* __restrict__ b2,
    float*       __restrict__ out,
    int n_nodes, int E, int n_tiles, int n_node_tiles)
{
    extern __shared__ __align__(16) char smc[];
    const uint32_t sb = smem_u32(smc);
    const int t   = threadIdx.x;
    const int wid = t >> 5;
    const int lid = t & 31;
    const int qr  = lid >> 2;
    const int ql  = lid & 3;
    const int wm  = wid & 3;       // M quadrant (rows wm*32..+32)
    const int wn  = wid >> 2;      // 0/1: h K-half AND output N-half
    const int lm  = lid & 7;
    const int lq3 = lid >> 3;
    const int lq4 = lid >> 4;

    // ======================= PHASE 1: node precompute =======================
    {
        {   // stage V (combined 256x64 weight) once: fp16 [256][144B]
            int c = t;
            const float* src = (c < 128) ? (W1 + c * D_IN1) : (W1 + (c - 128) * D_IN1 + 64);
            #pragma unroll
            for (int s = 0; s < 4; ++s) {
                float4 v0 = *(const float4*)(src + s * 16 + 0);
                float4 v1 = *(const float4*)(src + s * 16 + 4);
                float4 v2 = *(const float4*)(src + s * 16 + 8);
                float4 v3 = *(const float4*)(src + s * 16 + 12);
                uint4 pa = make_uint4(pack_h2(v0.x, v0.y), pack_h2(v0.z, v0.w),
                                      pack_h2(v1.x, v1.y), pack_h2(v1.z, v1.w));
                uint4 pb = make_uint4(pack_h2(v2.x, v2.y), pack_h2(v2.z, v2.w),
                                      pack_h2(v3.x, v3.y), pack_h2(v3.z, v3.w));
                *(uint4*)(smc + PRE_V_B + c * 144 + s * 32)      = pa;
                *(uint4*)(smc + PRE_V_B + c * 144 + s * 32 + 16) = pb;
            }
        }
        uint32_t ab[2];
        #pragma unroll
        for (int i = 0; i < 2; ++i)
            ab[i] = sb + PRE_XT_B + (uint32_t)((wm * 32 + i * 16 + ((lq3 & 1) << 3) + lm) * 144)
                  + (uint32_t)((lq3 >> 1) * 16);

        for (int nt = blockIdx.x; nt < n_node_tiles; nt += gridDim.x) {
            const int node0 = nt * 128;
            {   // stage x tile fp16 [128][144B] (streaming loads)
                int m = t >> 1, hs = t & 1;
                int gn = node0 + m;
                #pragma unroll
                for (int s = 0; s < 2; ++s) {
                    float4 v0, v1, v2, v3;
                    if (gn < n_nodes) {
                        const float4* src = (const float4*)(x + (size_t)gn * DIM_NODE + hs * 32 + s * 16);
                        v0 = __ldcs(src + 0); v1 = __ldcs(src + 1);
                        v2 = __ldcs(src + 2); v3 = __ldcs(src + 3);
                    } else {
                        v0 = v1 = v2 = v3 = make_float4(0.f, 0.f, 0.f, 0.f);
                    }
                    uint4 pa = make_uint4(pack_h2(v0.x, v0.y), pack_h2(v0.z, v0.w),
                                          pack_h2(v1.x, v1.y), pack_h2(v1.z, v1.w));
                    uint4 pb = make_uint4(pack_h2(v2.x, v2.y), pack_h2(v2.z, v2.w),
                                          pack_h2(v3.x, v3.y), pack_h2(v3.z, v3.w));
                    *(uint4*)(smc + PRE_XT_B + m * 144 + hs * 64 + s * 32)      = pa;
                    *(uint4*)(smc + PRE_XT_B + m * 144 + hs * 64 + s * 32 + 16) = pb;
                }
            }
            __syncthreads();

            #pragma unroll
            for (int nh = 0; nh < 2; ++nh) {
                if (nh) __syncthreads();
                float acc[2][8][4];
                #pragma unroll
                for (int i = 0; i < 2; ++i)
                    #pragma unroll
                    for (int j = 0; j < 8; ++j)
                        #pragma unroll
                        for (int c = 0; c < 4; ++c) acc[i][j][c] = 0.f;
                #pragma unroll
                for (int ks = 0; ks < 4; ++ks) {
                    uint32_t A[2][4], B[4][4];
                    ldsm_x4(A[0], ab[0] + ks * 32);
                    ldsm_x4(A[1], ab[1] + ks * 32);
                    #pragma unroll
                    for (int jj = 0; jj < 4; ++jj) {
                        int n = nh * 128 + wn * 64 + jj * 16 + lq4 * 8 + lm;
                        ldsm_x4(B[jj], sb + PRE_V_B + (uint32_t)(n * 144)
                                       + (uint32_t)((lq3 & 1) * 16) + ks * 32);
                    }
                    #pragma unroll
                    for (int i = 0; i < 2; ++i)
                        #pragma unroll
                        for (int j = 0; j < 8; ++j)
                            mma_f16(acc[i][j], A[i], &B[j >> 1][(j & 1) * 2]);
                }
                #pragma unroll
                for (int i = 0; i < 2; ++i) {
                    int r = wm * 32 + i * 16 + qr;
                    #pragma unroll
                    for (int j = 0; j < 8; ++j) {
                        int c = wn * 64 + j * 8 + 2 * ql;
                        *(uint32_t*)(smc + PRE_PH_B + r * 272 + 2 * c) =
                            pack_h2(acc[i][j][0], acc[i][j][1]);
                        *(uint32_t*)(smc + PRE_PH_B + (r + 8) * 272 + 2 * c) =
                            pack_h2(acc[i][j][2], acc[i][j][3]);
                    }
                }
                __syncthreads();
                {
                    int m = t >> 1, hs = t & 1;
                    int gn = node0 + m;
                    if (gn < n_nodes) {
                        const uint4* srcp = (const uint4*)(smc + PRE_PH_B + m * 272 + hs * 128);
                        uint4* dstp = (uint4*)((__half*)g_P + (size_t)gn * 256 + nh * 128 + hs * 64);
                        #pragma unroll
                        for (int s = 0; s < 8; ++s) dstp[s] = srcp[s];
                    }
                }
            }
            __syncthreads();
        }
    }

    // ======================= GRID BARRIER (epoch-based) ======================
    __threadfence();
    __syncthreads();
    if (t == 0) {
        unsigned v = *((volatile unsigned*)&g_barrier);
        unsigned target = (v / gridDim.x + 1u) * gridDim.x;
        atomicAdd(&g_barrier, 1u);
        while (*((volatile unsigned*)&g_barrier) < target) { }
    }
    __syncthreads();

    // ======================= PHASE 2 prologue: weights =======================
    {
        int n = t >> 1, hs = t & 1;
        const float4* src = (const float4*)(W1 + n * D_IN1 + 128 + hs * 16);
        float4 v0 = src[0], v1 = src[1], v2 = src[2], v3 = src[3];
        uint4 p0 = make_uint4(pack_h2(v0.x, v0.y), pack_h2(v0.z, v0.w),
                              pack_h2(v1.x, v1.y), pack_h2(v1.z, v1.w));
        uint4 p1 = make_uint4(pack_h2(v2.x, v2.y), pack_h2(v2.z, v2.w),
                              pack_h2(v3.x, v3.y), pack_h2(v3.z, v3.w));
        *(uint4*)(smc + W1C_B + n * 80 + hs * 32)      = p0;
        *(uint4*)(smc + W1C_B + n * 80 + hs * 32 + 16) = p1;
    }
    {
        int n = t >> 2, q = t & 3;
        const float4* src = (const float4*)(W2g + n * 128 + q * 32);
        #pragma unroll
        for (int s = 0; s < 2; ++s) {
            float4 v0 = src[4 * s + 0], v1 = src[4 * s + 1],
                   v2 = src[4 * s + 2], v3 = src[4 * s + 3];
            uint4 pa = make_uint4(pack_h2(v0.x, v0.y), pack_h2(v0.z, v0.w),
                                  pack_h2(v1.x, v1.y), pack_h2(v1.z, v1.w));
            uint4 pb = make_uint4(pack_h2(v2.x, v2.y), pack_h2(v2.z, v2.w),
                                  pack_h2(v3.x, v3.y), pack_h2(v3.z, v3.w));
            *(uint4*)(smc + W2_B + n * 272 + q * 64 + s * 32)      = pa;
            *(uint4*)(smc + W2_B + n * 272 + q * 64 + s * 32 + 16) = pb;
        }
    }
    if (t < 128)      ((float*)(smc + B1_B))[t] = b1[t];
    else if (t < 192) ((float*)(smc + B2_B))[t - 128] = b2[t - 128];
    __syncthreads();

    float2 bb2[4];
    #pragma unroll
    for (int j = 0; j < 4; ++j)
        bb2[j] = *(const float2*)((float*)(smc + B2_B) + wn * 32 + j * 8 + 2 * ql);
    const float4 bb1 = *(const float4*)((float*)(smc + B1_B) + 4 * lid);

    // ---- ldmatrix per-lane base addresses ----
    uint32_t a1b[2], b1b[4], a2o[2], b2b[2];
    #pragma unroll
    for (int i = 0; i < 2; ++i)
        a1b[i] = sb + EA_B + (uint32_t)((wm * 32 + i * 16 + ((lq3 & 1) << 3) + lm) * 80)
               + (uint32_t)((lq3 >> 1) * 16);
    #pragma unroll
    for (int jj = 0; jj < 4; ++jj)
        b1b[jj] = sb + W1C_B + (uint32_t)((wn * 64 + jj * 16 + lq4 * 8 + lm) * 80)
                + (uint32_t)((lq3 & 1) * 16);
    #pragma unroll
    for (int i = 0; i < 2; ++i)
        a2o[i] = sb + H_B + (uint32_t)((wm * 32 + i * 16 + ((lq3 & 1) << 3) + lm) * 272)
               + (uint32_t)((lq3 >> 1) * 16) + (uint32_t)((wn ^ 1) * 128);
    #pragma unroll
    for (int jj = 0; jj < 2; ++jj)
        b2b[jj] = sb + W2_B + (uint32_t)((wn * 32 + jj * 16 + lq4 * 8 + lm) * 272)
                + (uint32_t)((lq3 & 1) * 16);

    const int m0 = wid * 16;

    // ======================= PHASE 2: edge tile loop =========================
    for (int tile = blockIdx.x; tile < n_tiles; tile += gridDim.x) {
        const int ebase = tile * E_TILE;

        // ---- per-warp edge indices: lanes 0-15 src rows, 16-31 dst rows ----
        int my_idx = 0;
        {
            int eM = ebase + m0 + (lid & 15);
            if (eM < E) my_idx = (lid < 16) ? eidx[eM] : eidx[E + eM];
        }

        // ---- issue all Psum gather LDGs up front (latency overlaps staging) --
        uint2 us0[8], ud0[8], us1[8], ud1[8];
        #pragma unroll
        for (int r = 0; r < 8; ++r) {
            int si = __shfl_sync(0xffffffffu, my_idx, r);
            int di = __shfl_sync(0xffffffffu, my_idx, 16 + r);
            us0[r] = *(const uint2*)((const __half*)g_P + (size_t)si * 256 + 4 * lid);
            ud0[r] = *(const uint2*)((const __half*)g_P + (size_t)di * 256 + 128 + 4 * lid);
        }
        #pragma unroll
        for (int r = 0; r < 8; ++r) {
            int si = __shfl_sync(0xffffffffu, my_idx, 8 + r);
            int di = __shfl_sync(0xffffffffu, my_idx, 24 + r);
            us1[r] = *(const uint2*)((const __half*)g_P + (size_t)si * 256 + 4 * lid);
            ud1[r] = *(const uint2*)((const __half*)g_P + (size_t)di * 256 + 128 + 4 * lid);
        }

        // ---- stage ea -> fp16 [128][40h] (overlays H; streaming loads) ----
        {
            int m = t >> 1, hs = t & 1;
            int ge = ebase + m;
            float4 v0, v1, v2, v3;
            if (ge < E) {
                const float4* src = (const float4*)(ea + (size_t)ge * DIM_EDGE + hs * 16);
                v0 = __ldcs(src + 0); v1 = __ldcs(src + 1);
                v2 = __ldcs(src + 2); v3 = __ldcs(src + 3);
            } else {
                v0 = v1 = v2 = v3 = make_float4(0.f, 0.f, 0.f, 0.f);
            }
            uint4 p0 = make_uint4(pack_h2(v0.x, v0.y), pack_h2(v0.z, v0.w),
                                  pack_h2(v1.x, v1.y), pack_h2(v1.z, v1.w));
            uint4 p1 = make_uint4(pack_h2(v2.x, v2.y), pack_h2(v2.z, v2.w),
                                  pack_h2(v3.x, v3.y), pack_h2(v3.z, v3.w));
            *(uint4*)(smc + EA_B + m * 80 + hs * 32)      = p0;
            *(uint4*)(smc + EA_B + m * 80 + hs * 32 + 16) = p1;
        }

        // ---- Psum = fp16(P_src + P_dst + b1) -> PS ----
        #pragma unroll
        for (int r = 0; r < 8; ++r) {
            float2 s01 = h2f2(us0[r].x), s23 = h2f2(us0[r].y);
            float2 d01 = h2f2(ud0[r].x), d23 = h2f2(ud0[r].y);
            *(uint2*)(smc + PS_B + (m0 + r) * 272 + 8 * lid) =
                make_uint2(pack_h2(s01.x + d01.x + bb1.x, s01.y + d01.y + bb1.y),
                           pack_h2(s23.x + d23.x + bb1.z, s23.y + d23.y + bb1.w));
        }
        #pragma unroll
        for (int r = 0; r < 8; ++r) {
            float2 s01 = h2f2(us1[r].x), s23 = h2f2(us1[r].y);
            float2 d01 = h2f2(ud1[r].x), d23 = h2f2(ud1[r].y);
            *(uint2*)(smc + PS_B + (m0 + 8 + r) * 272 + 8 * lid) =
                make_uint2(pack_h2(s01.x + d01.x + bb1.x, s01.y + d01.y + bb1.y),
                           pack_h2(s23.x + d23.x + bb1.z, s23.y + d23.y + bb1.w));
        }
        __syncthreads();                       // (A) ea + PS staged

        // ---- GEMM1: C1[128x128] = ea @ W1c^T (per warp M=32, N=64) ----
        float acc1[2][8][4];
        #pragma unroll
        for (int i = 0; i < 2; ++i)
            #pragma unroll
            for (int j = 0; j < 8; ++j)
                #pragma unroll
                for (int c = 0; c < 4; ++c) acc1[i][j][c] = 0.f;

        #pragma unroll
        for (int ks = 0; ks < 2; ++ks) {
            uint32_t A[2][4], B[4][4];
            ldsm_x4(A[0], a1b[0] + ks * 32);
            ldsm_x4(A[1], a1b[1] + ks * 32);
            #pragma unroll
            for (int jj = 0; jj < 4; ++jj)
                ldsm_x4(B[jj], b1b[jj] + ks * 32);
            #pragma unroll
            for (int i = 0; i < 2; ++i)
                #pragma unroll
                for (int j = 0; j < 8; ++j)
                    mma_f16(acc1[i][j], A[i], &B[j >> 1][(j & 1) * 2]);
        }
        __syncthreads();                       // (B) EA reads done

        // ---- convert: h = leaky(C1 + Psum) -> GEMM2 A-frags + H STS ----
        uint32_t hA[2][4][4];
        #pragma unroll
        for (int i = 0; i < 2; ++i) {
            const int r0 = wm * 32 + i * 16 + qr;
            const int r1 = r0 + 8;
            #pragma unroll
            for (int ks = 0; ks < 4; ++ks) {
                #pragma unroll
                for (int jj = 0; jj < 2; ++jj) {
                    const int j = 2 * ks + jj;
                    const uint32_t off = (uint32_t)(wn * 128 + j * 16 + ql * 4);
                    float2 p0 = h2f2(*(const uint32_t*)(smc + PS_B + r0 * 272 + off));
                    float2 p1 = h2f2(*(const uint32_t*)(smc + PS_B + r1 * 272 + off));
                    float h0 = acc1[i][j][0] + p0.x;
                    float h1 = acc1[i][j][1] + p0.y;
                    float h2 = acc1[i][j][2] + p1.x;
                    float h3 = acc1[i][j][3] + p1.y;
                    h0 = (h0 >= 0.f) ? h0 : NEG_SLOPE * h0;
                    h1 = (h1 >= 0.f) ? h1 : NEG_SLOPE * h1;
                    h2 = (h2 >= 0.f) ? h2 : NEG_SLOPE * h2;
                    h3 = (h3 >= 0.f) ? h3 : NEG_SLOPE * h3;
                    uint32_t u0 = pack_h2(h0, h1);
                    uint32_t u1 = pack_h2(h2, h3);
                    hA[i][ks][jj * 2 + 0] = u0;
                    hA[i][ks][jj * 2 + 1] = u1;
                    *(uint32_t*)(smc + H_B + r0 * 272 + off) = u0;
                    *(uint32_t*)(smc + H_B + r1 * 272 + off) = u1;
                }
            }
        }
        __syncthreads();                       // (C) h visible for partner

        // ---- GEMM2: own K-half from regs, other via ldsm; M=32, N=32 ----
        float acc2[2][4][4];
        #pragma unroll
        for (int i = 0; i < 2; ++i)
            #pragma unroll
            for (int j = 0; j < 4; ++j)
                #pragma unroll
                for (int c = 0; c < 4; ++c) acc2[i][j][c] = 0.f;

        #pragma unroll
        for (int ksl = 0; ksl < 4; ++ksl) {
            uint32_t B[2][4];
            ldsm_x4(B[0], b2b[0] + (uint32_t)(wn * 128) + ksl * 32);
            ldsm_x4(B[1], b2b[1] + (uint32_t)(wn * 128) + ksl * 32);
            #pragma unroll
            for (int i = 0; i < 2; ++i)
                #pragma unroll
                for (int j = 0; j < 4; ++j)
                    mma_f16(acc2[i][j], hA[i][ksl], &B[j >> 1][(j & 1) * 2]);
        }
        #pragma unroll
        for (int ksl = 0; ksl < 4; ++ksl) {
            uint32_t A[2][4], B[2][4];
            ldsm_x4(A[0], a2o[0] + ksl * 32);
            ldsm_x4(A[1], a2o[1] + ksl * 32);
            ldsm_x4(B[0], b2b[0] + (uint32_t)((wn ^ 1) * 128) + ksl * 32);
            ldsm_x4(B[1], b2b[1] + (uint32_t)((wn ^ 1) * 128) + ksl * 32);
            #pragma unroll
            for (int i = 0; i < 2; ++i)
                #pragma unroll
                for (int j = 0; j < 4; ++j)
                    mma_f16(acc2[i][j], A[i], &B[j >> 1][(j & 1) * 2]);
        }

        // ---- Epilogue: direct STG (+b2), streaming stores ----
        #pragma unroll
        for (int i = 0; i < 2; ++i) {
            int r = wm * 32 + i * 16 + qr;
            int ge0 = ebase + r;
            int ge1 = ge0 + 8;
            #pragma unroll
            for (int j = 0; j < 4; ++j) {
                int c = wn * 32 + j * 8 + 2 * ql;
                if (ge0 < E)
                    __stcs((float2*)(out + (size_t)ge0 * OUT_DIM + c),
                           make_float2(acc2[i][j][0] + bb2[j].x, acc2[i][j][1] + bb2[j].y));
                if (ge1 < E)
                    __stcs((float2*)(out + (size_t)ge1 * OUT_DIM + c),
                           make_float2(acc2[i][j][2] + bb2[j].x, acc2[i][j][3] + bb2[j].y));
            }
        }
        __syncthreads();                       // (D) H/PS free for next tile
    }
}

// ---------------------------------------------------------------------------
extern "C" void kernel_launch(void* const* d_in, const int* in_sizes, int n_in,
                              void* d_out, int out_size)
{
    const float* x    = (const float*)d_in[0];
    const int*   eidx = (const int*)  d_in[1];
    const float* ea   = (const float*)d_in[2];
    const float* W1   = (const float*)d_in[3];
    const float* b1   = (const float*)d_in[4];
    const float* W2   = (const float*)d_in[5];
    const float* b2   = (const float*)d_in[6];
    float* out = (float*)d_out;

    int n_nodes = in_sizes[0] / DIM_NODE;
    if (n_nodes > MAX_NODES) n_nodes = MAX_NODES;
    int E = in_sizes[2] / DIM_EDGE;
    int n_tiles = (E + E_TILE - 1) / E_TILE;
    int n_node_tiles = (n_nodes + 127) / 128;

    static int n_sms = 0;
    if (n_sms == 0) {
        int dev = 0;
        cudaGetDevice(&dev);
        cudaDeviceGetAttribute(&n_sms, cudaDevAttrMultiProcessorCount, dev);
        if (n_sms <= 0) n_sms = 148;
    }
    int n_blocks = n_sms * 2;   // all resident (launch_bounds(256,2)) -> grid barrier safe

    cudaFuncSetAttribute(k_fused, cudaFuncAttributeMaxDynamicSharedMemorySize, (int)SMEM_BYTES);
    k_fused<<<n_blocks, 256, SMEM_BYTES>>>(x, eidx, ea, W1, b1, W2, b2, out,
                                           n_nodes, E, n_tiles, n_node_tiles);
}